// round 6
// baseline (speedup 1.0000x reference)
#include <cuda_runtime.h>
#include <mma.h>
#include <cstdint>

using namespace nvcuda;

namespace {
constexpr int E_TOT   = 100000;
constexpr int NSM     = 152;
constexpr int MT      = 64;
constexpr int TILES   = (E_TOT + MT - 1) / MT;   // 1563
constexpr int THREADS = 512;

constexpr int LDB = 68;    // weight panel 128 x 64
constexpr int LDE = 68;    // emb tile 64 x 64
constexpr int LDH = 132;   // h tile 64 x 128
constexpr int LDW = 324;   // w tile 64 x 320

constexpr int O_B = 0;                         // 2 panels * 128*68 = 17408
constexpr int O_E = O_B + 2 * 128 * LDB;       // 17408
constexpr int O_H = O_E + MT * LDE;            // 21760
constexpr int O_W = O_H + MT * LDH;            // 30208
constexpr int SMEM_FLOATS = O_W + MT * LDW;    // 50944
constexpr int SMEM_BYTES  = SMEM_FLOATS * 4;   // 203776
}

// 9 pre-rounded weight panels: [j][k(128)][c(64)]
__device__ float g_wp[9 * 128 * 64];

__device__ __forceinline__ float rtf32(float x) {
    uint32_t u;
    asm("cvt.rna.tf32.f32 %0, %1;" : "=r"(u) : "f"(x));
    return __uint_as_float(u);
}
__device__ __forceinline__ float silu_f(float x) {
    return x / (1.0f + __expf(-x));
}
__device__ __forceinline__ uint32_t smem_u32(const void* p) {
    uint32_t a;
    asm("{ .reg .u64 t; cvta.to.shared.u64 t, %1; cvt.u32.u64 %0, t; }"
        : "=r"(a) : "l"(p));
    return a;
}
__device__ __forceinline__ void cpa16(uint32_t d, const void* s) {
    asm volatile("cp.async.cg.shared.global [%0], [%1], 16;" :: "r"(d), "l"(s));
}
__device__ __forceinline__ void cpa_commit() {
    asm volatile("cp.async.commit_group;" ::: "memory");
}
__device__ __forceinline__ void cpa_wait0() {
    asm volatile("cp.async.wait_group 0;" ::: "memory");
}

using FragA = wmma::fragment<wmma::matrix_a, 16, 16, 8, wmma::precision::tf32, wmma::row_major>;
using FragB = wmma::fragment<wmma::matrix_b, 16, 16, 8, wmma::precision::tf32, wmma::row_major>;
using FragC = wmma::fragment<wmma::accumulator, 16, 16, 8, float>;

// ---------------- prep: tf32-round weights into panel layout ----------------
__global__ void prep_weights(const float* __restrict__ W0, const float* __restrict__ W1,
                             const float* __restrict__ P1, const float* __restrict__ P2,
                             const float* __restrict__ P3, const float* __restrict__ P4,
                             const float* __restrict__ P5)
{
    int i = blockIdx.x * blockDim.x + threadIdx.x;
    if (i >= 9 * 128 * 64) return;
    int j = i >> 13;
    int r = (i >> 6) & 127;
    int c = i & 63;
    float v = 0.0f;
    switch (j) {
        case 0: v = (r < 64) ? W0[r * 128 + c]      : 0.0f; break;
        case 1: v = (r < 64) ? W0[r * 128 + 64 + c] : 0.0f; break;
        case 2: v = W1[r * 128 + c];      break;
        case 3: v = W1[r * 128 + 64 + c]; break;
        case 4: v = P1[r * 64 + c]; break;
        case 5: v = P2[r * 64 + c]; break;
        case 6: v = P3[r * 64 + c]; break;
        case 7: v = P4[r * 64 + c]; break;
        default: v = P5[r * 64 + c]; break;
    }
    g_wp[i] = rtf32(v);
}

// ---------------- fused persistent kernel ----------------
__global__ void __launch_bounds__(THREADS, 1)
fused_tpmlp(const float* __restrict__ emb, const float* __restrict__ x1,
            const float* __restrict__ x2, float* __restrict__ out)
{
    extern __shared__ float sm[];
    const uint32_t sb = smem_u32(sm);
    const int tid  = threadIdx.x;
    const int warp = tid >> 5;
    const int rt   = warp & 3;     // 4 row tiles of 16
    const int ng   = warp >> 2;    // 4 col groups of 16 within a 64-col panel

    // issue cp.async for panel j into buffer b (128x64 f32 = 2048 f4, 4/thread)
    auto issue_panel = [&](int j, int b) {
        const float* src = g_wp + j * 8192;
        #pragma unroll
        for (int h = 0; h < 4; h++) {
            int q = tid + h * 512;
            int r = q >> 4, c4 = (q & 15) * 4;
            cpa16(sb + (uint32_t)(O_B + b * 128 * LDB + r * LDB + c4) * 4,
                  src + r * 64 + c4);
        }
        cpa_commit();
    };

    // emb register double-buffer: thread covers f4 idx tid, tid+512
    const int q0 = tid, q1 = tid + 512;
    const int er0 = q0 >> 4, ec0 = (q0 & 15) * 4;
    const int er1 = q1 >> 4, ec1 = (q1 & 15) * 4;
    float4 ea0, ea1;
    auto load_emb = [&](int t) {
        long g0 = (long)t * MT + er0;
        long g1 = (long)t * MT + er1;
        ea0 = (g0 < E_TOT) ? *(const float4*)(emb + g0 * 64 + ec0)
                           : make_float4(0.f, 0.f, 0.f, 0.f);
        ea1 = (g1 < E_TOT) ? *(const float4*)(emb + g1 * 64 + ec1)
                           : make_float4(0.f, 0.f, 0.f, 0.f);
    };
    load_emb(blockIdx.x);

    const float s1  = 0.125f;                // 1/sqrt(64)
    const float s2  = 0.08838834764831845f;  // 1/sqrt(128)
    const float inv = 0.08838834764831845f;  // folded GEMM3 scale

    const float INV_SQRT2 = 0.7071067811865476f;
    const float INV_SQRT3 = 0.5773502691896258f;
    const float INV_SQRT6 = 0.4082482904638631f;

    int buf = 0;
    issue_panel(0, 0);    // W0a for first tile

    for (int t = blockIdx.x; t < TILES; t += NSM) {
        // ---- STS emb tile (tf32) ----
        {
            float* d = sm + O_E + er0 * LDE + ec0;
            d[0] = rtf32(ea0.x); d[1] = rtf32(ea0.y); d[2] = rtf32(ea0.z); d[3] = rtf32(ea0.w);
            d = sm + O_E + er1 * LDE + ec1;
            d[0] = rtf32(ea1.x); d[1] = rtf32(ea1.y); d[2] = rtf32(ea1.z); d[3] = rtf32(ea1.w);
        }

        FragC acc2a, acc2b;    // G2 accumulators held across phases

        // ================= 9 weight phases =================
        #pragma unroll
        for (int j = 0; j < 9; j++) {
            cpa_wait0();
            __syncthreads();           // panel j ready + prior-phase hazards cleared
            // prefetch next panel (j+1, or W0a of next tile)
            if (j < 8)                  issue_panel(j + 1, buf ^ 1);
            else if (t + NSM < TILES)   issue_panel(0, buf ^ 1);
            else                        cpa_commit();   // keep group count consistent
            if (j == 0) load_emb(t + NSM < TILES ? t + NSM : t);  // next emb under G1a

            const float* B = sm + O_B + buf * 128 * LDB;

            if (j < 2) {
                // ---- G1 half j: h1[:, j*64+ng*16] = silu(emb @ W0h * s1) ----
                FragC acc;
                wmma::fill_fragment(acc, 0.0f);
                #pragma unroll
                for (int k = 0; k < 64; k += 8) {
                    FragA a;
                    wmma::load_matrix_sync(a, sm + O_E + rt * 16 * LDE + k, LDE);
                    FragB b;
                    wmma::load_matrix_sync(b, B + k * LDB + ng * 16, LDB);
                    wmma::mma_sync(acc, a, b, acc);
                }
                #pragma unroll
                for (int i = 0; i < acc.num_elements; i++)
                    acc.x[i] = rtf32(silu_f(acc.x[i] * s1));
                wmma::store_matrix_sync(sm + O_H + rt * 16 * LDH + j * 64 + ng * 16,
                                        acc, LDH, wmma::mem_row_major);
            } else if (j < 4) {
                // ---- G2 half (j-2): acc over full K=128 of h1 ----
                FragC* acc = (j == 2) ? &acc2a : &acc2b;
                wmma::fill_fragment(*acc, 0.0f);
                #pragma unroll
                for (int k = 0; k < 128; k += 8) {
                    FragA a;
                    wmma::load_matrix_sync(a, sm + O_H + rt * 16 * LDH + k, LDH);
                    FragB b;
                    wmma::load_matrix_sync(b, B + k * LDB + ng * 16, LDB);
                    wmma::mma_sync(*acc, a, b, *acc);
                }
                if (j == 3) {
                    __syncthreads();   // all h1 reads done before overwrite
                    #pragma unroll
                    for (int i = 0; i < acc2a.num_elements; i++)
                        acc2a.x[i] = rtf32(silu_f(acc2a.x[i] * s2) * inv);
                    #pragma unroll
                    for (int i = 0; i < acc2b.num_elements; i++)
                        acc2b.x[i] = rtf32(silu_f(acc2b.x[i] * s2) * inv);
                    wmma::store_matrix_sync(sm + O_H + rt * 16 * LDH + ng * 16,
                                            acc2a, LDH, wmma::mem_row_major);
                    wmma::store_matrix_sync(sm + O_H + rt * 16 * LDH + 64 + ng * 16,
                                            acc2b, LDH, wmma::mem_row_major);
                }
            } else {
                // ---- G3 panel p = j-4: w[:, p*64+ng*16] = h2 @ P_p ----
                const int p = j - 4;
                FragC acc;
                wmma::fill_fragment(acc, 0.0f);
                #pragma unroll
                for (int k = 0; k < 128; k += 8) {
                    FragA a;
                    wmma::load_matrix_sync(a, sm + O_H + rt * 16 * LDH + k, LDH);
                    FragB b;
                    wmma::load_matrix_sync(b, B + k * LDB + ng * 16, LDB);
                    wmma::mma_sync(acc, a, b, acc);
                }
                wmma::store_matrix_sync(sm + O_W + rt * 16 * LDW + p * 64 + ng * 16,
                                        acc, LDW, wmma::mem_row_major);
            }
            buf ^= 1;
        }
        __syncthreads();   // sW complete

        // ================= fused TP epilogue =================
        const long g0 = (long)t * MT;
        #pragma unroll
        for (int h = 0; h < 8; h++) {
            int idx = tid + h * 512;          // 4096 tasks: 64 rows x 64 u
            int r = idx >> 6, u = idx & 63;
            long g = g0 + r;
            if (g >= E_TOT) continue;

            const float* x1r = x1 + g * 256;
            float x10 = x1r[u];
            float a0 = x1r[64 + 3 * u + 0];
            float a1 = x1r[64 + 3 * u + 1];
            float a2 = x1r[64 + 3 * u + 2];
            float4 t2 = *(const float4*)(x2 + g * 4);
            float b0 = t2.x, c0 = t2.y, c1 = t2.z, c2 = t2.w;

            const float* wr = sm + O_W + r * LDW;
            float w1 = wr[u];
            float w2 = wr[64 + u];
            float w3 = wr[128 + u];
            float w4 = wr[192 + u];
            float w5 = wr[256 + u];

            float* o = out + g * 448;
            float dot = a0 * c0 + a1 * c1 + a2 * c2;

            o[u] = INV_SQRT2 * (w1 * x10 * b0 + w4 * dot * INV_SQRT3);

            o[64 + 3 * u + 0] = INV_SQRT2 * (w2 * a0 * b0 + w3 * x10 * c0);
            o[64 + 3 * u + 1] = INV_SQRT2 * (w2 * a1 * b0 + w3 * x10 * c1);
            o[64 + 3 * u + 2] = INV_SQRT2 * (w2 * a2 * b0 + w3 * x10 * c2);

            float r0 = a1 * c2 - a2 * c1;
            float r1 = a2 * c0 - a0 * c2;
            float r2 = a0 * c1 - a1 * c0;
            o[256 + 3 * u + 0] = w5 * r0 * INV_SQRT6;
            o[256 + 3 * u + 1] = w5 * r1 * INV_SQRT6;
            o[256 + 3 * u + 2] = w5 * r2 * INV_SQRT6;
        }
        // no barrier needed here: next sW write is 5 phase-syncs away
    }
}

extern "C" void kernel_launch(void* const* d_in, const int* in_sizes, int n_in,
                              void* d_out, int out_size) {
    (void)in_sizes; (void)n_in; (void)out_size;
    const float* emb = (const float*)d_in[0];
    const float* x1  = (const float*)d_in[1];
    const float* x2  = (const float*)d_in[2];
    const float* W0  = (const float*)d_in[3];
    const float* W1  = (const float*)d_in[4];
    const float* P1  = (const float*)d_in[5];
    const float* P2  = (const float*)d_in[6];
    const float* P3  = (const float*)d_in[7];
    const float* P4  = (const float*)d_in[8];
    const float* P5  = (const float*)d_in[9];
    float* out = (float*)d_out;

    cudaFuncSetAttribute(fused_tpmlp,
                         cudaFuncAttributeMaxDynamicSharedMemorySize, SMEM_BYTES);

    prep_weights<<<(9 * 128 * 64 + 255) / 256, 256>>>(W0, W1, P1, P2, P3, P4, P5);
    fused_tpmlp<<<NSM, THREADS, SMEM_BYTES>>>(emb, x1, x2, out);
}

// round 8
// speedup vs baseline: 4.5658x; 4.5658x over previous
#include <cuda_runtime.h>
#include <cuda_fp16.h>
#include <mma.h>
#include <cstdint>

using namespace nvcuda;

namespace {
constexpr int E_TOT   = 100000;
constexpr int NSM     = 152;
constexpr int MT      = 64;
constexpr int TILES   = (E_TOT + MT - 1) / MT;   // 1563
constexpr int THREADS = 512;

// leading dims (elements) — fp16 LDs must be multiples of 8 (wmma rule)
constexpr int LDW0 = 136;   // halves
constexpr int LDW1 = 136;   // halves
constexpr int LDP  = 328;   // halves (2 chunks of 160, +8 pad)
constexpr int LDE  = 72;    // halves
constexpr int LDH  = 136;   // halves
constexpr int LDX  = 164;   // floats (mod-4 rule)

// byte offsets (all 32B aligned)
constexpr int O_W0 = 0;                          // 64*136*2  = 17408
constexpr int O_W1 = O_W0 + 64  * LDW0 * 2;      // 17408
constexpr int O_P  = O_W1 + 128 * LDW1 * 2;      // 52224
constexpr int O_E  = O_P  + 128 * LDP  * 2;      // 136192
constexpr int O_H  = O_E  + MT  * LDE  * 2;      // 145408
constexpr int O_X  = O_H  + MT  * LDH  * 2;      // 162816
constexpr int SMEM_BYTES = O_X + MT * LDX * 4;   // 204800
}

__device__ __forceinline__ float silu_f(float x) {
    return x / (1.0f + __expf(-x));
}

using FragA = wmma::fragment<wmma::matrix_a, 16, 16, 16, __half, wmma::row_major>;
using FragB = wmma::fragment<wmma::matrix_b, 16, 16, 16, __half, wmma::row_major>;
using FragC = wmma::fragment<wmma::accumulator, 16, 16, 16, float>;

__device__ __forceinline__ void st_h4(__half* d, float4 v) {
    __half2 lo = __floats2half2_rn(v.x, v.y);
    __half2 hi = __floats2half2_rn(v.z, v.w);
    uint2 u;
    u.x = *reinterpret_cast<uint32_t*>(&lo);
    u.y = *reinterpret_cast<uint32_t*>(&hi);
    *reinterpret_cast<uint2*>(d) = u;
}

__global__ void __launch_bounds__(THREADS, 1)
fused_fp16(const float* __restrict__ emb, const float* __restrict__ x1,
           const float* __restrict__ x2, const float* __restrict__ W0,
           const float* __restrict__ W1,
           const float* __restrict__ P1, const float* __restrict__ P2,
           const float* __restrict__ P3, const float* __restrict__ P4,
           const float* __restrict__ P5, float* __restrict__ out)
{
    extern __shared__ char smc[];
    __half* sW0 = reinterpret_cast<__half*>(smc + O_W0);
    __half* sW1 = reinterpret_cast<__half*>(smc + O_W1);
    __half* sP  = reinterpret_cast<__half*>(smc + O_P);
    __half* sE  = reinterpret_cast<__half*>(smc + O_E);
    __half* sH  = reinterpret_cast<__half*>(smc + O_H);
    float*  sX  = reinterpret_cast<float*>(smc + O_X);

    const int tid  = threadIdx.x;
    const int warp = tid >> 5;
    const int rt   = warp & 3;     // 4 row tiles of 16
    const int ng   = warp >> 2;    // 4 n groups

    // ---------------- stage all weights once (fp16) ----------------
    for (int q = tid; q < 64 * 32; q += THREADS) {          // W0 [64 x 128]
        int k = q >> 5, c4 = (q & 31) * 4;
        st_h4(sW0 + k * LDW0 + c4, *(const float4*)(W0 + k * 128 + c4));
    }
    for (int q = tid; q < 128 * 32; q += THREADS) {         // W1 [128 x 128]
        int k = q >> 5, c4 = (q & 31) * 4;
        st_h4(sW1 + k * LDW1 + c4, *(const float4*)(W1 + k * 128 + c4));
    }
    {   // Pcat [128 x 320]: col j = c*160 + p*32 + uu  <->  P_p[k][c*32+uu]
        const float* Ps[5] = {P1, P2, P3, P4, P5};
        for (int q = tid; q < 128 * 80; q += THREADS) {
            int k  = q / 80;
            int j4 = (q % 80) * 4;
            int c  = j4 / 160, jj = j4 % 160;
            int p  = jj >> 5,  uu = jj & 31;
            st_h4(sP + k * LDP + j4,
                  *(const float4*)(Ps[p] + k * 64 + c * 32 + uu));
        }
    }

    // emb register double-buffer: thread covers f4 idx tid, tid+512
    const int q0 = tid, q1 = tid + 512;
    const int er0 = q0 >> 4, ec0 = (q0 & 15) * 4;
    const int er1 = q1 >> 4, ec1 = (q1 & 15) * 4;
    float4 ea0, ea1;
    auto load_emb = [&](int t) {
        long g0 = (long)t * MT + er0;
        long g1 = (long)t * MT + er1;
        ea0 = (g0 < E_TOT) ? *(const float4*)(emb + g0 * 64 + ec0)
                           : make_float4(0.f, 0.f, 0.f, 0.f);
        ea1 = (g1 < E_TOT) ? *(const float4*)(emb + g1 * 64 + ec1)
                           : make_float4(0.f, 0.f, 0.f, 0.f);
    };
    load_emb(blockIdx.x);

    const float s1  = 0.125f;                // 1/sqrt(64)
    const float s2  = 0.08838834764831845f;  // 1/sqrt(128)
    const float inv = 0.08838834764831845f;  // folded GEMM3 scale

    const float INV_SQRT2 = 0.7071067811865476f;
    const float INV_SQRT3 = 0.5773502691896258f;
    const float INV_SQRT6 = 0.4082482904638631f;

    for (int t = blockIdx.x; t < TILES; t += NSM) {
        // ---- phase A: STS emb tile (fp16) ----
        st_h4(sE + er0 * LDE + ec0, ea0);
        st_h4(sE + er1 * LDE + ec1, ea1);
        __syncthreads();
        load_emb(t + NSM < TILES ? t + NSM : t);

        // ---- G1: acc = emb @ W0  -> sX (fp32 raw) ----
        {
            FragC acc[2];
            #pragma unroll
            for (int n = 0; n < 2; n++) wmma::fill_fragment(acc[n], 0.0f);
            #pragma unroll
            for (int k = 0; k < 64; k += 16) {
                FragA a;
                wmma::load_matrix_sync(a, sE + rt * 16 * LDE + k, LDE);
                #pragma unroll
                for (int n = 0; n < 2; n++) {
                    FragB b;
                    wmma::load_matrix_sync(b, sW0 + k * LDW0 + ng * 32 + n * 16, LDW0);
                    wmma::mma_sync(acc[n], a, b, acc[n]);
                }
            }
            #pragma unroll
            for (int n = 0; n < 2; n++)
                wmma::store_matrix_sync(sX + rt * 16 * LDX + ng * 32 + n * 16,
                                        acc[n], LDX, wmma::mem_row_major);
        }
        __syncthreads();

        // ---- convert 1: sH = fp16(silu(sX * s1)) ----
        for (int q = tid; q < MT * 32; q += THREADS) {
            int r = q >> 5, c4 = (q & 31) * 4;
            float4 v = *(const float4*)(sX + r * LDX + c4);
            v.x = silu_f(v.x * s1); v.y = silu_f(v.y * s1);
            v.z = silu_f(v.z * s1); v.w = silu_f(v.w * s1);
            st_h4(sH + r * LDH + c4, v);
        }
        __syncthreads();

        // ---- G2: acc = h1 @ W1 -> sX ----
        {
            FragC acc[2];
            #pragma unroll
            for (int n = 0; n < 2; n++) wmma::fill_fragment(acc[n], 0.0f);
            #pragma unroll
            for (int k = 0; k < 128; k += 16) {
                FragA a;
                wmma::load_matrix_sync(a, sH + rt * 16 * LDH + k, LDH);
                #pragma unroll
                for (int n = 0; n < 2; n++) {
                    FragB b;
                    wmma::load_matrix_sync(b, sW1 + k * LDW1 + ng * 32 + n * 16, LDW1);
                    wmma::mma_sync(acc[n], a, b, acc[n]);
                }
            }
            #pragma unroll
            for (int n = 0; n < 2; n++)
                wmma::store_matrix_sync(sX + rt * 16 * LDX + ng * 32 + n * 16,
                                        acc[n], LDX, wmma::mem_row_major);
        }
        __syncthreads();

        // ---- convert 2: sH = fp16(silu(sX * s2) * inv) ----
        for (int q = tid; q < MT * 32; q += THREADS) {
            int r = q >> 5, c4 = (q & 31) * 4;
            float4 v = *(const float4*)(sX + r * LDX + c4);
            v.x = silu_f(v.x * s2) * inv; v.y = silu_f(v.y * s2) * inv;
            v.z = silu_f(v.z * s2) * inv; v.w = silu_f(v.w * s2) * inv;
            st_h4(sH + r * LDH + c4, v);
        }
        __syncthreads();

        const long g0 = (long)t * MT;

        // ---- G3 + epilogue: 2 chunks of 160 cols (= 32 u each) ----
        #pragma unroll
        for (int c = 0; c < 2; c++) {
            {   // w = h2 @ Pcat[c]: 40 warp-tiles (4 rt x 10 nt), warp does nt=ng,ng+4(,ng+8)
                const int ncnt = (ng < 2) ? 3 : 2;
                FragC acc[3];
                for (int s = 0; s < ncnt; s++) wmma::fill_fragment(acc[s], 0.0f);
                #pragma unroll
                for (int k = 0; k < 128; k += 16) {
                    FragA a;
                    wmma::load_matrix_sync(a, sH + rt * 16 * LDH + k, LDH);
                    for (int s = 0; s < ncnt; s++) {
                        int nt = ng + s * 4;
                        FragB b;
                        wmma::load_matrix_sync(b, sP + k * LDP + c * 160 + nt * 16, LDP);
                        wmma::mma_sync(acc[s], a, b, acc[s]);
                    }
                }
                for (int s = 0; s < ncnt; s++) {
                    int nt = ng + s * 4;
                    wmma::store_matrix_sync(sX + rt * 16 * LDX + nt * 16,
                                            acc[s], LDX, wmma::mem_row_major);
                }
            }
            __syncthreads();

            // epilogue: u in [c*32, c*32+32), w_p at sX col p*32+uu
            #pragma unroll
            for (int h = 0; h < 4; h++) {
                int idx = tid + h * 512;          // 2048 tasks: 64 rows x 32 u
                int r = idx >> 5, uu = idx & 31;
                int u = c * 32 + uu;
                long g = g0 + r;
                if (g >= E_TOT) continue;

                const float* x1r = x1 + g * 256;
                float x10 = x1r[u];
                float a0 = x1r[64 + 3 * u + 0];
                float a1 = x1r[64 + 3 * u + 1];
                float a2 = x1r[64 + 3 * u + 2];
                float4 t2 = *(const float4*)(x2 + g * 4);
                float b0 = t2.x, c0v = t2.y, c1v = t2.z, c2v = t2.w;

                const float* wr = sX + r * LDX;
                float w1 = wr[uu];
                float w2 = wr[32 + uu];
                float w3 = wr[64 + uu];
                float w4 = wr[96 + uu];
                float w5 = wr[128 + uu];

                float* o = out + g * 448;
                float dot = a0 * c0v + a1 * c1v + a2 * c2v;

                o[u] = INV_SQRT2 * (w1 * x10 * b0 + w4 * dot * INV_SQRT3);

                o[64 + 3 * u + 0] = INV_SQRT2 * (w2 * a0 * b0 + w3 * x10 * c0v);
                o[64 + 3 * u + 1] = INV_SQRT2 * (w2 * a1 * b0 + w3 * x10 * c1v);
                o[64 + 3 * u + 2] = INV_SQRT2 * (w2 * a2 * b0 + w3 * x10 * c2v);

                float r0 = a1 * c2v - a2 * c1v;
                float r1 = a2 * c0v - a0 * c2v;
                float r2 = a0 * c1v - a1 * c0v;
                o[256 + 3 * u + 0] = w5 * r0 * INV_SQRT6;
                o[256 + 3 * u + 1] = w5 * r1 * INV_SQRT6;
                o[256 + 3 * u + 2] = w5 * r2 * INV_SQRT6;
            }
            __syncthreads();
        }
    }
}

extern "C" void kernel_launch(void* const* d_in, const int* in_sizes, int n_in,
                              void* d_out, int out_size) {
    (void)in_sizes; (void)n_in; (void)out_size;
    const float* emb = (const float*)d_in[0];
    const float* x1  = (const float*)d_in[1];
    const float* x2  = (const float*)d_in[2];
    const float* W0  = (const float*)d_in[3];
    const float* W1  = (const float*)d_in[4];
    const float* P1  = (const float*)d_in[5];
    const float* P2  = (const float*)d_in[6];
    const float* P3  = (const float*)d_in[7];
    const float* P4  = (const float*)d_in[8];
    const float* P5  = (const float*)d_in[9];
    float* out = (float*)d_out;

    cudaFuncSetAttribute(fused_fp16,
                         cudaFuncAttributeMaxDynamicSharedMemorySize, SMEM_BYTES);

    fused_fp16<<<NSM, THREADS, SMEM_BYTES>>>(emb, x1, x2, W0, W1,
                                             P1, P2, P3, P4, P5, out);
}

// round 9
// speedup vs baseline: 4.6179x; 1.0114x over previous
#include <cuda_runtime.h>
#include <cuda_fp16.h>
#include <mma.h>
#include <cstdint>

using namespace nvcuda;

namespace {
constexpr int E_TOT   = 100000;
constexpr int NSM     = 152;
constexpr int MT      = 64;
constexpr int TILES   = (E_TOT + MT - 1) / MT;   // 1563
constexpr int THREADS = 512;

// leading dims (elements) — fp16 LDs multiples of 8, fp32 multiples of 4
constexpr int LDW0 = 136;   // halves
constexpr int LDW1 = 136;   // halves
constexpr int LDP  = 328;   // halves
constexpr int LDE  = 72;    // halves
constexpr int LDH  = 136;   // halves
constexpr int LDX  = 164;   // floats
constexpr int LDS_SCR = 36; // floats, warp scratch 16x32 (+4 pad)

// byte offsets
constexpr int O_W0 = 0;                          // 17408
constexpr int O_W1 = O_W0 + 64  * LDW0 * 2;      // 17408
constexpr int O_P  = O_W1 + 128 * LDW1 * 2;      // 52224
constexpr int O_E  = O_P  + 128 * LDP  * 2;      // 136192
constexpr int O_H1 = O_E  + MT  * LDE  * 2;      // 145408
constexpr int O_H2 = O_H1 + MT  * LDH  * 2;      // 162816
constexpr int O_X  = O_H2 + MT  * LDH  * 2;      // 180224 (w buffer; also warp scratch)
constexpr int SMEM_BYTES = O_X + MT * LDX * 4;   // 222208
}

__device__ __forceinline__ float silu_f(float x) {
    return x / (1.0f + __expf(-x));
}

using FragA = wmma::fragment<wmma::matrix_a, 16, 16, 16, __half, wmma::row_major>;
using FragB = wmma::fragment<wmma::matrix_b, 16, 16, 16, __half, wmma::row_major>;
using FragC = wmma::fragment<wmma::accumulator, 16, 16, 16, float>;

__device__ __forceinline__ void st_h4(__half* d, float4 v) {
    __half2 lo = __floats2half2_rn(v.x, v.y);
    __half2 hi = __floats2half2_rn(v.z, v.w);
    uint2 u;
    u.x = *reinterpret_cast<uint32_t*>(&lo);
    u.y = *reinterpret_cast<uint32_t*>(&hi);
    *reinterpret_cast<uint2*>(d) = u;
}

__global__ void __launch_bounds__(THREADS, 1)
fused_fp16(const float* __restrict__ emb, const float* __restrict__ x1,
           const float* __restrict__ x2, const float* __restrict__ W0,
           const float* __restrict__ W1,
           const float* __restrict__ P1, const float* __restrict__ P2,
           const float* __restrict__ P3, const float* __restrict__ P4,
           const float* __restrict__ P5, float* __restrict__ out)
{
    extern __shared__ char smc[];
    __half* sW0 = reinterpret_cast<__half*>(smc + O_W0);
    __half* sW1 = reinterpret_cast<__half*>(smc + O_W1);
    __half* sP  = reinterpret_cast<__half*>(smc + O_P);
    __half* sE  = reinterpret_cast<__half*>(smc + O_E);
    __half* sH1 = reinterpret_cast<__half*>(smc + O_H1);
    __half* sH2 = reinterpret_cast<__half*>(smc + O_H2);
    float*  sX  = reinterpret_cast<float*>(smc + O_X);

    const int tid  = threadIdx.x;
    const int warp = tid >> 5;
    const int lane = tid & 31;
    const int rt   = warp & 3;     // 4 row tiles of 16
    const int ng   = warp >> 2;    // 4 n groups
    float* scr = sX + warp * (16 * LDS_SCR);   // per-warp 16x32 fp32 scratch

    // ---------------- stage all weights once (fp16) ----------------
    for (int q = tid; q < 64 * 32; q += THREADS) {          // W0 [64 x 128]
        int k = q >> 5, c4 = (q & 31) * 4;
        st_h4(sW0 + k * LDW0 + c4, *(const float4*)(W0 + k * 128 + c4));
    }
    for (int q = tid; q < 128 * 32; q += THREADS) {         // W1 [128 x 128]
        int k = q >> 5, c4 = (q & 31) * 4;
        st_h4(sW1 + k * LDW1 + c4, *(const float4*)(W1 + k * 128 + c4));
    }
    {   // Pcat [128 x 320]: col j = c*160 + p*32 + uu  <->  P_p[k][c*32+uu]
        const float* Ps[5] = {P1, P2, P3, P4, P5};
        for (int q = tid; q < 128 * 80; q += THREADS) {
            int k  = q / 80;
            int j4 = (q % 80) * 4;
            int c  = j4 / 160, jj = j4 % 160;
            int p  = jj >> 5,  uu = jj & 31;
            st_h4(sP + k * LDP + j4,
                  *(const float4*)(Ps[p] + k * 64 + c * 32 + uu));
        }
    }

    // emb register double-buffer: thread covers f4 idx tid, tid+512
    const int q0 = tid, q1 = tid + 512;
    const int er0 = q0 >> 4, ec0 = (q0 & 15) * 4;
    const int er1 = q1 >> 4, ec1 = (q1 & 15) * 4;
    float4 ea0, ea1;
    auto load_emb = [&](int t) {
        long g0 = (long)t * MT + er0;
        long g1 = (long)t * MT + er1;
        ea0 = (g0 < E_TOT) ? *(const float4*)(emb + g0 * 64 + ec0)
                           : make_float4(0.f, 0.f, 0.f, 0.f);
        ea1 = (g1 < E_TOT) ? *(const float4*)(emb + g1 * 64 + ec1)
                           : make_float4(0.f, 0.f, 0.f, 0.f);
    };
    load_emb(blockIdx.x);

    const float s1  = 0.125f;                // 1/sqrt(64)
    const float s2  = 0.08838834764831845f;  // 1/sqrt(128)
    const float inv = 0.08838834764831845f;  // folded GEMM3 scale

    const float INV_SQRT2 = 0.7071067811865476f;
    const float INV_SQRT3 = 0.5773502691896258f;
    const float INV_SQRT6 = 0.4082482904638631f;

    // warp-local convert geometry: lane -> (row, colblock)
    const int cr = lane >> 1;            // 0..15
    const int cc = (lane & 1) * 16;      // 0 or 16

    for (int t = blockIdx.x; t < TILES; t += NSM) {
        // ---- STS emb tile (fp16); barrier also fences prior epilogue sX reads ----
        st_h4(sE + er0 * LDE + ec0, ea0);
        st_h4(sE + er1 * LDE + ec1, ea1);
        __syncthreads();
        load_emb(t + NSM < TILES ? t + NSM : t);

        // ---- G1: emb @ W0 -> warp scratch -> silu -> sH1 (fp16) ----
        {
            FragC acc[2];
            #pragma unroll
            for (int n = 0; n < 2; n++) wmma::fill_fragment(acc[n], 0.0f);
            #pragma unroll
            for (int k = 0; k < 64; k += 16) {
                FragA a;
                wmma::load_matrix_sync(a, sE + rt * 16 * LDE + k, LDE);
                #pragma unroll
                for (int n = 0; n < 2; n++) {
                    FragB b;
                    wmma::load_matrix_sync(b, sW0 + k * LDW0 + ng * 32 + n * 16, LDW0);
                    wmma::mma_sync(acc[n], a, b, acc[n]);
                }
            }
            wmma::store_matrix_sync(scr,      acc[0], LDS_SCR, wmma::mem_row_major);
            wmma::store_matrix_sync(scr + 16, acc[1], LDS_SCR, wmma::mem_row_major);
            __syncwarp();
            const float* s = scr + cr * LDS_SCR + cc;
            __half* d = sH1 + (rt * 16 + cr) * LDH + ng * 32 + cc;
            #pragma unroll
            for (int j = 0; j < 4; j++) {
                float4 v = *(const float4*)(s + j * 4);
                v.x = silu_f(v.x * s1); v.y = silu_f(v.y * s1);
                v.z = silu_f(v.z * s1); v.w = silu_f(v.w * s1);
                st_h4(d + j * 4, v);
            }
        }
        __syncthreads();

        // ---- G2: h1 @ W1 -> scratch -> silu*inv -> sH2 (fp16) ----
        {
            FragC acc[2];
            #pragma unroll
            for (int n = 0; n < 2; n++) wmma::fill_fragment(acc[n], 0.0f);
            #pragma unroll
            for (int k = 0; k < 128; k += 16) {
                FragA a;
                wmma::load_matrix_sync(a, sH1 + rt * 16 * LDH + k, LDH);
                #pragma unroll
                for (int n = 0; n < 2; n++) {
                    FragB b;
                    wmma::load_matrix_sync(b, sW1 + k * LDW1 + ng * 32 + n * 16, LDW1);
                    wmma::mma_sync(acc[n], a, b, acc[n]);
                }
            }
            wmma::store_matrix_sync(scr,      acc[0], LDS_SCR, wmma::mem_row_major);
            wmma::store_matrix_sync(scr + 16, acc[1], LDS_SCR, wmma::mem_row_major);
            __syncwarp();
            const float* s = scr + cr * LDS_SCR + cc;
            __half* d = sH2 + (rt * 16 + cr) * LDH + ng * 32 + cc;
            #pragma unroll
            for (int j = 0; j < 4; j++) {
                float4 v = *(const float4*)(s + j * 4);
                v.x = silu_f(v.x * s2) * inv; v.y = silu_f(v.y * s2) * inv;
                v.z = silu_f(v.z * s2) * inv; v.w = silu_f(v.w * s2) * inv;
                st_h4(d + j * 4, v);
            }
        }
        __syncthreads();

        const long g0 = (long)t * MT;

        // ---- G3 + epilogue: 2 chunks of 160 cols (= 32 u each) ----
        #pragma unroll
        for (int c = 0; c < 2; c++) {
            {   // w = h2 @ Pcat[c]
                const int ncnt = (ng < 2) ? 3 : 2;
                FragC acc[3];
                for (int s = 0; s < ncnt; s++) wmma::fill_fragment(acc[s], 0.0f);
                #pragma unroll
                for (int k = 0; k < 128; k += 16) {
                    FragA a;
                    wmma::load_matrix_sync(a, sH2 + rt * 16 * LDH + k, LDH);
                    for (int s = 0; s < ncnt; s++) {
                        int nt = ng + s * 4;
                        FragB b;
                        wmma::load_matrix_sync(b, sP + k * LDP + c * 160 + nt * 16, LDP);
                        wmma::mma_sync(acc[s], a, b, acc[s]);
                    }
                }
                for (int s = 0; s < ncnt; s++) {
                    int nt = ng + s * 4;
                    wmma::store_matrix_sync(sX + rt * 16 * LDX + nt * 16,
                                            acc[s], LDX, wmma::mem_row_major);
                }
            }
            __syncthreads();

            // ---- epilogue, batched loads first (hide LDG latency) ----
            float x10v[4], av[12];
            #pragma unroll
            for (int h = 0; h < 4; h++) {
                int idx = tid + h * 512;
                int r = idx >> 5, uu = idx & 31;
                int u = c * 32 + uu;
                long g = g0 + r;
                if (g < E_TOT) {
                    const float* x1r = x1 + g * 256;
                    x10v[h]      = x1r[u];
                    av[3 * h + 0] = x1r[64 + 3 * u + 0];
                    av[3 * h + 1] = x1r[64 + 3 * u + 1];
                    av[3 * h + 2] = x1r[64 + 3 * u + 2];
                } else {
                    x10v[h] = av[3 * h] = av[3 * h + 1] = av[3 * h + 2] = 0.f;
                }
            }
            #pragma unroll
            for (int h = 0; h < 4; h++) {
                int idx = tid + h * 512;
                int r = idx >> 5, uu = idx & 31;
                int u = c * 32 + uu;
                long g = g0 + r;
                if (g >= E_TOT) continue;

                float4 t2 = *(const float4*)(x2 + g * 4);
                float b0 = t2.x, c0v = t2.y, c1v = t2.z, c2v = t2.w;

                float x10 = x10v[h];
                float a0 = av[3 * h + 0], a1 = av[3 * h + 1], a2 = av[3 * h + 2];

                const float* wr = sX + r * LDX;
                float w1 = wr[uu];
                float w2 = wr[32 + uu];
                float w3 = wr[64 + uu];
                float w4 = wr[96 + uu];
                float w5 = wr[128 + uu];

                float* o = out + g * 448;
                float dot = a0 * c0v + a1 * c1v + a2 * c2v;

                o[u] = INV_SQRT2 * (w1 * x10 * b0 + w4 * dot * INV_SQRT3);

                o[64 + 3 * u + 0] = INV_SQRT2 * (w2 * a0 * b0 + w3 * x10 * c0v);
                o[64 + 3 * u + 1] = INV_SQRT2 * (w2 * a1 * b0 + w3 * x10 * c1v);
                o[64 + 3 * u + 2] = INV_SQRT2 * (w2 * a2 * b0 + w3 * x10 * c2v);

                float r0 = a1 * c2v - a2 * c1v;
                float r1 = a2 * c0v - a0 * c2v;
                float r2 = a0 * c1v - a1 * c0v;
                o[256 + 3 * u + 0] = w5 * r0 * INV_SQRT6;
                o[256 + 3 * u + 1] = w5 * r1 * INV_SQRT6;
                o[256 + 3 * u + 2] = w5 * r2 * INV_SQRT6;
            }
            if (c == 0) __syncthreads();   // sX reused by chunk 1; chunk-1 reads fenced by loop-top barrier
        }
    }
}

extern "C" void kernel_launch(void* const* d_in, const int* in_sizes, int n_in,
                              void* d_out, int out_size) {
    (void)in_sizes; (void)n_in; (void)out_size;
    const float* emb = (const float*)d_in[0];
    const float* x1  = (const float*)d_in[1];
    const float* x2  = (const float*)d_in[2];
    const float* W0  = (const float*)d_in[3];
    const float* W1  = (const float*)d_in[4];
    const float* P1  = (const float*)d_in[5];
    const float* P2  = (const float*)d_in[6];
    const float* P3  = (const float*)d_in[7];
    const float* P4  = (const float*)d_in[8];
    const float* P5  = (const float*)d_in[9];
    float* out = (float*)d_out;

    cudaFuncSetAttribute(fused_fp16,
                         cudaFuncAttributeMaxDynamicSharedMemorySize, SMEM_BYTES);

    fused_fp16<<<NSM, THREADS, SMEM_BYTES>>>(emb, x1, x2, W0, W1,
                                             P1, P2, P3, P4, P5, out);
}

// round 10
// speedup vs baseline: 5.1181x; 1.1083x over previous
#include <cuda_runtime.h>
#include <cuda_fp16.h>
#include <mma.h>
#include <cstdint>

using namespace nvcuda;

namespace {
constexpr int E_TOT   = 100000;
constexpr int NSM     = 152;
constexpr int MT      = 64;
constexpr int TILES   = (E_TOT + MT - 1) / MT;   // 1563
constexpr int THREADS = 512;

// leading dims (elements) — fp16 LDs multiples of 8, fp32 multiples of 4
constexpr int LDW0 = 136;   // halves
constexpr int LDW1 = 136;   // halves
constexpr int LDP  = 328;   // halves
constexpr int LDE  = 72;    // halves
constexpr int LDH  = 136;   // halves
constexpr int LDX  = 164;   // floats
constexpr int LDS_SCR = 36; // floats, warp scratch 16x32 (+4 pad)

// byte offsets
constexpr int O_W0 = 0;                          // 17408
constexpr int O_W1 = O_W0 + 64  * LDW0 * 2;      // 17408
constexpr int O_P  = O_W1 + 128 * LDW1 * 2;      // 52224
constexpr int O_E  = O_P  + 128 * LDP  * 2;      // 136192
constexpr int O_H1 = O_E  + MT  * LDE  * 2;      // 145408
constexpr int O_H2 = O_H1 + MT  * LDH  * 2;      // 162816
constexpr int O_X  = O_H2 + MT  * LDH  * 2;      // 180224 (w buffer; also warp scratch)
constexpr int SMEM_BYTES = O_X + MT * LDX * 4;   // 222208
}

__device__ __forceinline__ float silu_f(float x) {
    return __fdividef(x, 1.0f + __expf(-x));
}

using FragA = wmma::fragment<wmma::matrix_a, 16, 16, 16, __half, wmma::row_major>;
using FragB = wmma::fragment<wmma::matrix_b, 16, 16, 16, __half, wmma::row_major>;
using FragC = wmma::fragment<wmma::accumulator, 16, 16, 16, float>;

__device__ __forceinline__ void st_h4(__half* d, float4 v) {
    __half2 lo = __floats2half2_rn(v.x, v.y);
    __half2 hi = __floats2half2_rn(v.z, v.w);
    uint2 u;
    u.x = *reinterpret_cast<uint32_t*>(&lo);
    u.y = *reinterpret_cast<uint32_t*>(&hi);
    *reinterpret_cast<uint2*>(d) = u;
}

__global__ void __launch_bounds__(THREADS, 1)
fused_fp16(const float* __restrict__ emb, const float* __restrict__ x1,
           const float* __restrict__ x2, const float* __restrict__ W0,
           const float* __restrict__ W1,
           const float* __restrict__ P1, const float* __restrict__ P2,
           const float* __restrict__ P3, const float* __restrict__ P4,
           const float* __restrict__ P5, float* __restrict__ out)
{
    extern __shared__ char smc[];
    __half* sW0 = reinterpret_cast<__half*>(smc + O_W0);
    __half* sW1 = reinterpret_cast<__half*>(smc + O_W1);
    __half* sP  = reinterpret_cast<__half*>(smc + O_P);
    __half* sE  = reinterpret_cast<__half*>(smc + O_E);
    __half* sH1 = reinterpret_cast<__half*>(smc + O_H1);
    __half* sH2 = reinterpret_cast<__half*>(smc + O_H2);
    float*  sX  = reinterpret_cast<float*>(smc + O_X);

    const int tid  = threadIdx.x;
    const int warp = tid >> 5;
    const int lane = tid & 31;
    const int rt   = warp & 3;     // 4 row tiles of 16
    const int ng   = warp >> 2;    // 4 n groups
    float* scr = sX + warp * (16 * LDS_SCR);   // per-warp 16x32 fp32 scratch

    // ---------------- stage all weights once (fp16) ----------------
    for (int q = tid; q < 64 * 32; q += THREADS) {          // W0 [64 x 128]
        int k = q >> 5, c4 = (q & 31) * 4;
        st_h4(sW0 + k * LDW0 + c4, *(const float4*)(W0 + k * 128 + c4));
    }
    for (int q = tid; q < 128 * 32; q += THREADS) {         // W1 [128 x 128]
        int k = q >> 5, c4 = (q & 31) * 4;
        st_h4(sW1 + k * LDW1 + c4, *(const float4*)(W1 + k * 128 + c4));
    }
    {   // Pcat [128 x 320]: col j = c*160 + p*32 + uu  <->  P_p[k][c*32+uu]
        const float* Ps[5] = {P1, P2, P3, P4, P5};
        for (int q = tid; q < 128 * 80; q += THREADS) {
            int k  = q / 80;
            int j4 = (q % 80) * 4;
            int c  = j4 / 160, jj = j4 % 160;
            int p  = jj >> 5,  uu = jj & 31;
            st_h4(sP + k * LDP + j4,
                  *(const float4*)(Ps[p] + k * 64 + c * 32 + uu));
        }
    }

    // emb register double-buffer: thread covers f4 idx tid, tid+512
    const int q0 = tid, q1 = tid + 512;
    const int er0 = q0 >> 4, ec0 = (q0 & 15) * 4;
    const int er1 = q1 >> 4, ec1 = (q1 & 15) * 4;
    float4 ea0, ea1;
    auto load_emb = [&](int t) {
        long g0 = (long)t * MT + er0;
        long g1 = (long)t * MT + er1;
        ea0 = (g0 < E_TOT) ? *(const float4*)(emb + g0 * 64 + ec0)
                           : make_float4(0.f, 0.f, 0.f, 0.f);
        ea1 = (g1 < E_TOT) ? *(const float4*)(emb + g1 * 64 + ec1)
                           : make_float4(0.f, 0.f, 0.f, 0.f);
    };
    load_emb(blockIdx.x);

    const float s1  = 0.125f;                // 1/sqrt(64)
    const float s2  = 0.08838834764831845f;  // 1/sqrt(128)
    const float inv = 0.08838834764831845f;  // folded GEMM3 scale

    const float INV_SQRT2 = 0.7071067811865476f;
    const float INV_SQRT3 = 0.5773502691896258f;
    const float INV_SQRT6 = 0.4082482904638631f;

    // warp-local convert geometry: lane -> (row, colblock)
    const int cr = lane >> 1;            // 0..15
    const int cc = (lane & 1) * 16;      // 0 or 16

    for (int t = blockIdx.x; t < TILES; t += NSM) {
        // ---- STS emb tile (fp16); barrier also fences prior epilogue sX reads ----
        st_h4(sE + er0 * LDE + ec0, ea0);
        st_h4(sE + er1 * LDE + ec1, ea1);
        __syncthreads();
        load_emb(t + NSM < TILES ? t + NSM : t);

        // ---- G1: emb @ W0 -> warp scratch -> silu -> sH1 (fp16) ----
        {
            FragC acc[2];
            #pragma unroll
            for (int n = 0; n < 2; n++) wmma::fill_fragment(acc[n], 0.0f);
            #pragma unroll
            for (int k = 0; k < 64; k += 16) {
                FragA a;
                wmma::load_matrix_sync(a, sE + rt * 16 * LDE + k, LDE);
                #pragma unroll
                for (int n = 0; n < 2; n++) {
                    FragB b;
                    wmma::load_matrix_sync(b, sW0 + k * LDW0 + ng * 32 + n * 16, LDW0);
                    wmma::mma_sync(acc[n], a, b, acc[n]);
                }
            }
            wmma::store_matrix_sync(scr,      acc[0], LDS_SCR, wmma::mem_row_major);
            wmma::store_matrix_sync(scr + 16, acc[1], LDS_SCR, wmma::mem_row_major);
            __syncwarp();
            const float* s = scr + cr * LDS_SCR + cc;
            __half* d = sH1 + (rt * 16 + cr) * LDH + ng * 32 + cc;
            #pragma unroll
            for (int j = 0; j < 4; j++) {
                float4 v = *(const float4*)(s + j * 4);
                v.x = silu_f(v.x * s1); v.y = silu_f(v.y * s1);
                v.z = silu_f(v.z * s1); v.w = silu_f(v.w * s1);
                st_h4(d + j * 4, v);
            }
        }
        __syncthreads();

        // ---- G2: h1 @ W1 -> scratch -> silu*inv -> sH2 (fp16) ----
        {
            FragC acc[2];
            #pragma unroll
            for (int n = 0; n < 2; n++) wmma::fill_fragment(acc[n], 0.0f);
            #pragma unroll
            for (int k = 0; k < 128; k += 16) {
                FragA a;
                wmma::load_matrix_sync(a, sH1 + rt * 16 * LDH + k, LDH);
                #pragma unroll
                for (int n = 0; n < 2; n++) {
                    FragB b;
                    wmma::load_matrix_sync(b, sW1 + k * LDW1 + ng * 32 + n * 16, LDW1);
                    wmma::mma_sync(acc[n], a, b, acc[n]);
                }
            }
            wmma::store_matrix_sync(scr,      acc[0], LDS_SCR, wmma::mem_row_major);
            wmma::store_matrix_sync(scr + 16, acc[1], LDS_SCR, wmma::mem_row_major);
            __syncwarp();
            const float* s = scr + cr * LDS_SCR + cc;
            __half* d = sH2 + (rt * 16 + cr) * LDH + ng * 32 + cc;
            #pragma unroll
            for (int j = 0; j < 4; j++) {
                float4 v = *(const float4*)(s + j * 4);
                v.x = silu_f(v.x * s2) * inv; v.y = silu_f(v.y * s2) * inv;
                v.z = silu_f(v.z * s2) * inv; v.w = silu_f(v.w * s2) * inv;
                st_h4(d + j * 4, v);
            }
        }
        __syncthreads();

        const long g0 = (long)t * MT;

        // ---- G3 + epilogue: 2 chunks of 160 cols (= 32 u each) ----
        #pragma unroll
        for (int c = 0; c < 2; c++) {
            // ---- PREFETCH epilogue inputs for this chunk BEFORE the MMA ----
            // (x1/x2 don't depend on sX; their ~600-cycle latency hides under MMA)
            float x10v[4], av[12];
            float4 x2v[4];
            #pragma unroll
            for (int h = 0; h < 4; h++) {
                int idx = tid + h * 512;
                int r = idx >> 5, uu = idx & 31;
                int u = c * 32 + uu;
                long g = g0 + r;
                if (g < E_TOT) {
                    const float* x1r = x1 + g * 256;
                    x10v[h]       = x1r[u];
                    av[3 * h + 0] = x1r[64 + 3 * u + 0];
                    av[3 * h + 1] = x1r[64 + 3 * u + 1];
                    av[3 * h + 2] = x1r[64 + 3 * u + 2];
                    x2v[h] = *(const float4*)(x2 + g * 4);
                } else {
                    x10v[h] = av[3 * h] = av[3 * h + 1] = av[3 * h + 2] = 0.f;
                    x2v[h] = make_float4(0.f, 0.f, 0.f, 0.f);
                }
            }

            {   // w = h2 @ Pcat[c]
                const int ncnt = (ng < 2) ? 3 : 2;
                FragC acc[3];
                for (int s = 0; s < ncnt; s++) wmma::fill_fragment(acc[s], 0.0f);
                #pragma unroll
                for (int k = 0; k < 128; k += 16) {
                    FragA a;
                    wmma::load_matrix_sync(a, sH2 + rt * 16 * LDH + k, LDH);
                    for (int s = 0; s < ncnt; s++) {
                        int nt = ng + s * 4;
                        FragB b;
                        wmma::load_matrix_sync(b, sP + k * LDP + c * 160 + nt * 16, LDP);
                        wmma::mma_sync(acc[s], a, b, acc[s]);
                    }
                }
                for (int s = 0; s < ncnt; s++) {
                    int nt = ng + s * 4;
                    wmma::store_matrix_sync(sX + rt * 16 * LDX + nt * 16,
                                            acc[s], LDX, wmma::mem_row_major);
                }
            }
            __syncthreads();

            // ---- epilogue: consume prefetched regs + sX ----
            #pragma unroll
            for (int h = 0; h < 4; h++) {
                int idx = tid + h * 512;
                int r = idx >> 5, uu = idx & 31;
                int u = c * 32 + uu;
                long g = g0 + r;
                if (g >= E_TOT) continue;

                float b0 = x2v[h].x, c0v = x2v[h].y, c1v = x2v[h].z, c2v = x2v[h].w;
                float x10 = x10v[h];
                float a0 = av[3 * h + 0], a1 = av[3 * h + 1], a2 = av[3 * h + 2];

                const float* wr = sX + r * LDX;
                float w1 = wr[uu];
                float w2 = wr[32 + uu];
                float w3 = wr[64 + uu];
                float w4 = wr[96 + uu];
                float w5 = wr[128 + uu];

                float* o = out + g * 448;
                float dot = a0 * c0v + a1 * c1v + a2 * c2v;

                o[u] = INV_SQRT2 * (w1 * x10 * b0 + w4 * dot * INV_SQRT3);

                o[64 + 3 * u + 0] = INV_SQRT2 * (w2 * a0 * b0 + w3 * x10 * c0v);
                o[64 + 3 * u + 1] = INV_SQRT2 * (w2 * a1 * b0 + w3 * x10 * c1v);
                o[64 + 3 * u + 2] = INV_SQRT2 * (w2 * a2 * b0 + w3 * x10 * c2v);

                float r0 = a1 * c2v - a2 * c1v;
                float r1 = a2 * c0v - a0 * c2v;
                float r2 = a0 * c1v - a1 * c0v;
                o[256 + 3 * u + 0] = w5 * r0 * INV_SQRT6;
                o[256 + 3 * u + 1] = w5 * r1 * INV_SQRT6;
                o[256 + 3 * u + 2] = w5 * r2 * INV_SQRT6;
            }
            if (c == 0) __syncthreads();   // sX reused by chunk 1; chunk-1 reads fenced by loop-top barrier
        }
    }
}

extern "C" void kernel_launch(void* const* d_in, const int* in_sizes, int n_in,
                              void* d_out, int out_size) {
    (void)in_sizes; (void)n_in; (void)out_size;
    const float* emb = (const float*)d_in[0];
    const float* x1  = (const float*)d_in[1];
    const float* x2  = (const float*)d_in[2];
    const float* W0  = (const float*)d_in[3];
    const float* W1  = (const float*)d_in[4];
    const float* P1  = (const float*)d_in[5];
    const float* P2  = (const float*)d_in[6];
    const float* P3  = (const float*)d_in[7];
    const float* P4  = (const float*)d_in[8];
    const float* P5  = (const float*)d_in[9];
    float* out = (float*)d_out;

    cudaFuncSetAttribute(fused_fp16,
                         cudaFuncAttributeMaxDynamicSharedMemorySize, SMEM_BYTES);

    fused_fp16<<<NSM, THREADS, SMEM_BYTES>>>(emb, x1, x2, W0, W1,
                                             P1, P2, P3, P4, P5, out);
}

// round 11
// speedup vs baseline: 6.0334x; 1.1788x over previous
#include <cuda_runtime.h>
#include <cuda_fp16.h>
#include <mma.h>
#include <cstdint>

using namespace nvcuda;

namespace {
constexpr int E_TOT   = 100000;
constexpr int NSM     = 152;
constexpr int MT      = 32;                       // rows per half-pipeline tile
constexpr int TILES   = E_TOT / MT;               // 3125 exact
constexpr int NWORK   = NSM * 2;                  // 304 pipelines
constexpr int THREADS = 512;

// leading dims (elements)
constexpr int LDW0 = 136;   // halves
constexpr int LDW1 = 136;   // halves
constexpr int LDP  = 328;   // halves
constexpr int LDE  = 72;    // halves
constexpr int LDH  = 136;   // halves
constexpr int LDX  = 164;   // floats
constexpr int LDS_SCR = 36; // floats, warp scratch 16x32 (+4)

// byte offsets
constexpr int O_W0 = 0;                           // 17408
constexpr int O_W1 = O_W0 + 64  * LDW0 * 2;       // 17408
constexpr int O_P  = O_W1 + 128 * LDW1 * 2;       // 52224
constexpr int O_T  = O_P  + 128 * LDP  * 2;       // 136192
// per-half tile block
constexpr int H_E  = 0;                           // 32*72*2  = 4608
constexpr int H_H1 = H_E  + MT * LDE * 2;         // 4608
constexpr int H_H2 = H_H1 + MT * LDH * 2;         // 13312
constexpr int H_X  = H_H2 + MT * LDH * 2;         // 22016
constexpr int HB   = H_X  + MT * LDX * 4;         // 43008
constexpr int SMEM_BYTES = O_T + 2 * HB;          // 222208
}

__device__ __forceinline__ float silu_f(float x) {
    return __fdividef(x, 1.0f + __expf(-x));
}

using FragA = wmma::fragment<wmma::matrix_a, 16, 16, 16, __half, wmma::row_major>;
using FragB = wmma::fragment<wmma::matrix_b, 16, 16, 16, __half, wmma::row_major>;
using FragC = wmma::fragment<wmma::accumulator, 16, 16, 16, float>;

__device__ __forceinline__ void st_h4(__half* d, float4 v) {
    __half2 lo = __floats2half2_rn(v.x, v.y);
    __half2 hi = __floats2half2_rn(v.z, v.w);
    uint2 u;
    u.x = *reinterpret_cast<uint32_t*>(&lo);
    u.y = *reinterpret_cast<uint32_t*>(&hi);
    *reinterpret_cast<uint2*>(d) = u;
}
__device__ __forceinline__ void hbar(int id) {
    asm volatile("bar.sync %0, 256;" :: "r"(id) : "memory");
}

__global__ void __launch_bounds__(THREADS, 1)
fused_fp16(const float* __restrict__ emb, const float* __restrict__ x1,
           const float* __restrict__ x2, const float* __restrict__ W0,
           const float* __restrict__ W1,
           const float* __restrict__ P1, const float* __restrict__ P2,
           const float* __restrict__ P3, const float* __restrict__ P4,
           const float* __restrict__ P5, float* __restrict__ out)
{
    extern __shared__ char smc[];
    __half* sW0 = reinterpret_cast<__half*>(smc + O_W0);
    __half* sW1 = reinterpret_cast<__half*>(smc + O_W1);
    __half* sP  = reinterpret_cast<__half*>(smc + O_P);

    const int tid  = threadIdx.x;
    const int warp = tid >> 5;
    const int lane = tid & 31;

    // ---------------- stage all weights once (full block) ----------------
    for (int q = tid; q < 64 * 32; q += THREADS) {
        int k = q >> 5, c4 = (q & 31) * 4;
        st_h4(sW0 + k * LDW0 + c4, *(const float4*)(W0 + k * 128 + c4));
    }
    for (int q = tid; q < 128 * 32; q += THREADS) {
        int k = q >> 5, c4 = (q & 31) * 4;
        st_h4(sW1 + k * LDW1 + c4, *(const float4*)(W1 + k * 128 + c4));
    }
    {
        const float* Ps[5] = {P1, P2, P3, P4, P5};
        for (int q = tid; q < 128 * 80; q += THREADS) {
            int k  = q / 80;
            int j4 = (q % 80) * 4;
            int c  = j4 / 160, jj = j4 % 160;
            int p  = jj >> 5,  uu = jj & 31;
            st_h4(sP + k * LDP + j4,
                  *(const float4*)(Ps[p] + k * 64 + c * 32 + uu));
        }
    }
    __syncthreads();

    // ---------------- per-half pipeline setup ----------------
    const int half = warp >> 3;            // 0 or 1
    const int wl   = warp & 7;             // warp within half
    const int ltid = tid & 255;            // thread within half
    const int rt   = wl & 1;               // 2 row tiles of 16
    const int ng   = wl >> 1;              // 4 n groups
    const int bid  = half + 1;             // named barrier id

    char* hB = smc + O_T + half * HB;
    __half* sE  = reinterpret_cast<__half*>(hB + H_E);
    __half* sH1 = reinterpret_cast<__half*>(hB + H_H1);
    __half* sH2 = reinterpret_cast<__half*>(hB + H_H2);
    float*  sX  = reinterpret_cast<float*>(hB + H_X);
    float*  scr = sX + wl * (16 * LDS_SCR);

    // emb register double-buffer: 512 f4 per tile, thread covers ltid, ltid+256
    const int q0 = ltid, q1 = ltid + 256;
    const int er0 = q0 >> 4, ec0 = (q0 & 15) * 4;
    const int er1 = q1 >> 4, ec1 = (q1 & 15) * 4;
    float4 ea0, ea1;
    auto load_emb = [&](int t) {
        long g0 = (long)t * MT + er0;
        long g1 = (long)t * MT + er1;
        ea0 = *(const float4*)(emb + g0 * 64 + ec0);
        ea1 = *(const float4*)(emb + g1 * 64 + ec1);
    };

    const int w0 = blockIdx.x * 2 + half;     // pipeline id 0..303
    if (w0 < TILES) load_emb(w0);

    const float s1  = 0.125f;
    const float s2  = 0.08838834764831845f;
    const float inv = 0.08838834764831845f;

    const float INV_SQRT2 = 0.7071067811865476f;
    const float INV_SQRT3 = 0.5773502691896258f;
    const float INV_SQRT6 = 0.4082482904638631f;

    const int cr = lane >> 1;
    const int cc = (lane & 1) * 16;

    for (int t = w0; t < TILES; t += NWORK) {
        // ---- STS emb tile; barrier fences prior epilogue sX reads too ----
        st_h4(sE + er0 * LDE + ec0, ea0);
        st_h4(sE + er1 * LDE + ec1, ea1);
        hbar(bid);
        if (t + NWORK < TILES) load_emb(t + NWORK);

        // ---- G1: emb @ W0 -> scratch -> silu -> sH1 ----
        {
            FragC acc[2];
            #pragma unroll
            for (int n = 0; n < 2; n++) wmma::fill_fragment(acc[n], 0.0f);
            #pragma unroll
            for (int k = 0; k < 64; k += 16) {
                FragA a;
                wmma::load_matrix_sync(a, sE + rt * 16 * LDE + k, LDE);
                #pragma unroll
                for (int n = 0; n < 2; n++) {
                    FragB b;
                    wmma::load_matrix_sync(b, sW0 + k * LDW0 + ng * 32 + n * 16, LDW0);
                    wmma::mma_sync(acc[n], a, b, acc[n]);
                }
            }
            wmma::store_matrix_sync(scr,      acc[0], LDS_SCR, wmma::mem_row_major);
            wmma::store_matrix_sync(scr + 16, acc[1], LDS_SCR, wmma::mem_row_major);
            __syncwarp();
            const float* s = scr + cr * LDS_SCR + cc;
            __half* d = sH1 + (rt * 16 + cr) * LDH + ng * 32 + cc;
            #pragma unroll
            for (int j = 0; j < 4; j++) {
                float4 v = *(const float4*)(s + j * 4);
                v.x = silu_f(v.x * s1); v.y = silu_f(v.y * s1);
                v.z = silu_f(v.z * s1); v.w = silu_f(v.w * s1);
                st_h4(d + j * 4, v);
            }
        }
        hbar(bid);

        // ---- G2: h1 @ W1 -> scratch -> silu*inv -> sH2 ----
        {
            FragC acc[2];
            #pragma unroll
            for (int n = 0; n < 2; n++) wmma::fill_fragment(acc[n], 0.0f);
            #pragma unroll
            for (int k = 0; k < 128; k += 16) {
                FragA a;
                wmma::load_matrix_sync(a, sH1 + rt * 16 * LDH + k, LDH);
                #pragma unroll
                for (int n = 0; n < 2; n++) {
                    FragB b;
                    wmma::load_matrix_sync(b, sW1 + k * LDW1 + ng * 32 + n * 16, LDW1);
                    wmma::mma_sync(acc[n], a, b, acc[n]);
                }
            }
            wmma::store_matrix_sync(scr,      acc[0], LDS_SCR, wmma::mem_row_major);
            wmma::store_matrix_sync(scr + 16, acc[1], LDS_SCR, wmma::mem_row_major);
            __syncwarp();
            const float* s = scr + cr * LDS_SCR + cc;
            __half* d = sH2 + (rt * 16 + cr) * LDH + ng * 32 + cc;
            #pragma unroll
            for (int j = 0; j < 4; j++) {
                float4 v = *(const float4*)(s + j * 4);
                v.x = silu_f(v.x * s2) * inv; v.y = silu_f(v.y * s2) * inv;
                v.z = silu_f(v.z * s2) * inv; v.w = silu_f(v.w * s2) * inv;
                st_h4(d + j * 4, v);
            }
        }
        hbar(bid);

        const long g0 = (long)t * MT;

        // ---- G3 + epilogue: 2 chunks of 160 cols (32 u each) ----
        #pragma unroll
        for (int c = 0; c < 2; c++) {
            // prefetch epilogue inputs (hide LDG under MMA)
            float x10v[4], av[12];
            float4 x2v[4];
            #pragma unroll
            for (int h = 0; h < 4; h++) {
                int idx = ltid + h * 256;         // 1024 tasks: 32 rows x 32 u
                int r = idx >> 5, uu = idx & 31;
                int u = c * 32 + uu;
                long g = g0 + r;
                const float* x1r = x1 + g * 256;
                x10v[h]       = x1r[u];
                av[3 * h + 0] = x1r[64 + 3 * u + 0];
                av[3 * h + 1] = x1r[64 + 3 * u + 1];
                av[3 * h + 2] = x1r[64 + 3 * u + 2];
                x2v[h] = *(const float4*)(x2 + g * 4);
            }

            {   // w = h2 @ Pcat[c]
                const int ncnt = (ng < 2) ? 3 : 2;
                FragC acc[3];
                for (int s = 0; s < ncnt; s++) wmma::fill_fragment(acc[s], 0.0f);
                #pragma unroll
                for (int k = 0; k < 128; k += 16) {
                    FragA a;
                    wmma::load_matrix_sync(a, sH2 + rt * 16 * LDH + k, LDH);
                    for (int s = 0; s < ncnt; s++) {
                        int nt = ng + s * 4;
                        FragB b;
                        wmma::load_matrix_sync(b, sP + k * LDP + c * 160 + nt * 16, LDP);
                        wmma::mma_sync(acc[s], a, b, acc[s]);
                    }
                }
                for (int s = 0; s < ncnt; s++) {
                    int nt = ng + s * 4;
                    wmma::store_matrix_sync(sX + rt * 16 * LDX + nt * 16,
                                            acc[s], LDX, wmma::mem_row_major);
                }
            }
            hbar(bid);

            // ---- epilogue ----
            #pragma unroll
            for (int h = 0; h < 4; h++) {
                int idx = ltid + h * 256;
                int r = idx >> 5, uu = idx & 31;
                int u = c * 32 + uu;
                long g = g0 + r;

                float b0 = x2v[h].x, c0v = x2v[h].y, c1v = x2v[h].z, c2v = x2v[h].w;
                float x10 = x10v[h];
                float a0 = av[3 * h + 0], a1 = av[3 * h + 1], a2 = av[3 * h + 2];

                const float* wr = sX + r * LDX;
                float w1 = wr[uu];
                float w2 = wr[32 + uu];
                float w3 = wr[64 + uu];
                float w4 = wr[96 + uu];
                float w5 = wr[128 + uu];

                float* o = out + g * 448;
                float dot = a0 * c0v + a1 * c1v + a2 * c2v;

                o[u] = INV_SQRT2 * (w1 * x10 * b0 + w4 * dot * INV_SQRT3);

                o[64 + 3 * u + 0] = INV_SQRT2 * (w2 * a0 * b0 + w3 * x10 * c0v);
                o[64 + 3 * u + 1] = INV_SQRT2 * (w2 * a1 * b0 + w3 * x10 * c1v);
                o[64 + 3 * u + 2] = INV_SQRT2 * (w2 * a2 * b0 + w3 * x10 * c2v);

                float r0 = a1 * c2v - a2 * c1v;
                float r1 = a2 * c0v - a0 * c2v;
                float r2 = a0 * c1v - a1 * c0v;
                o[256 + 3 * u + 0] = w5 * r0 * INV_SQRT6;
                o[256 + 3 * u + 1] = w5 * r1 * INV_SQRT6;
                o[256 + 3 * u + 2] = w5 * r2 * INV_SQRT6;
            }
            if (c == 0) hbar(bid);   // sX reused by chunk 1; loop-top barrier fences chunk-1 reads
        }
    }
}

extern "C" void kernel_launch(void* const* d_in, const int* in_sizes, int n_in,
                              void* d_out, int out_size) {
    (void)in_sizes; (void)n_in; (void)out_size;
    const float* emb = (const float*)d_in[0];
    const float* x1  = (const float*)d_in[1];
    const float* x2  = (const float*)d_in[2];
    const float* W0  = (const float*)d_in[3];
    const float* W1  = (const float*)d_in[4];
    const float* P1  = (const float*)d_in[5];
    const float* P2  = (const float*)d_in[6];
    const float* P3  = (const float*)d_in[7];
    const float* P4  = (const float*)d_in[8];
    const float* P5  = (const float*)d_in[9];
    float* out = (float*)d_out;

    cudaFuncSetAttribute(fused_fp16,
                         cudaFuncAttributeMaxDynamicSharedMemorySize, SMEM_BYTES);

    fused_fp16<<<NSM, THREADS, SMEM_BYTES>>>(emb, x1, x2, W0, W1,
                                             P1, P2, P3, P4, P5, out);
}

// round 12
// speedup vs baseline: 6.9994x; 1.1601x over previous
#include <cuda_runtime.h>
#include <cuda_fp16.h>
#include <mma.h>
#include <cstdint>

using namespace nvcuda;

namespace {
constexpr int E_TOT   = 100000;
constexpr int NSM     = 152;
constexpr int MT      = 16;                       // rows per pipeline tile
constexpr int TILES   = E_TOT / MT;               // 6250 exact
constexpr int NPIPE   = 4;
constexpr int NWORK   = NSM * NPIPE;              // 608 pipelines
constexpr int THREADS = 512;

// leading dims (elements)
constexpr int LDW0 = 136;   // halves
constexpr int LDW1 = 136;   // halves
constexpr int LDP  = 328;   // halves
constexpr int LDE  = 72;    // halves
constexpr int LDH  = 136;   // halves
constexpr int LDX  = 164;   // floats
constexpr int LDS_SCR = 36; // floats, warp scratch 16x32 (+4)

// byte offsets
constexpr int O_W0 = 0;                           // 17408
constexpr int O_W1 = O_W0 + 64  * LDW0 * 2;       // 17408
constexpr int O_P  = O_W1 + 128 * LDW1 * 2;       // 52224
constexpr int O_T  = O_P  + 128 * LDP  * 2;       // 136192
// per-pipeline tile block
constexpr int H_E  = 0;                           // 16*72*2  = 2304
constexpr int H_H1 = H_E  + MT * LDE * 2;         // 2304
constexpr int H_H2 = H_H1 + MT * LDH * 2;         // 6656
constexpr int H_X  = H_H2 + MT * LDH * 2;         // 11008
constexpr int HB   = H_X  + MT * LDX * 4;         // 21504
constexpr int SMEM_BYTES = O_T + NPIPE * HB;      // 222208
}

__device__ __forceinline__ float silu_f(float x) {
    return __fdividef(x, 1.0f + __expf(-x));
}

using FragA = wmma::fragment<wmma::matrix_a, 16, 16, 16, __half, wmma::row_major>;
using FragB = wmma::fragment<wmma::matrix_b, 16, 16, 16, __half, wmma::row_major>;
using FragC = wmma::fragment<wmma::accumulator, 16, 16, 16, float>;

__device__ __forceinline__ void st_h4(__half* d, float4 v) {
    __half2 lo = __floats2half2_rn(v.x, v.y);
    __half2 hi = __floats2half2_rn(v.z, v.w);
    uint2 u;
    u.x = *reinterpret_cast<uint32_t*>(&lo);
    u.y = *reinterpret_cast<uint32_t*>(&hi);
    *reinterpret_cast<uint2*>(d) = u;
}
__device__ __forceinline__ void pbar(int id) {
    asm volatile("bar.sync %0, 128;" :: "r"(id) : "memory");
}

__global__ void __launch_bounds__(THREADS, 1)
fused_fp16(const float* __restrict__ emb, const float* __restrict__ x1,
           const float* __restrict__ x2, const float* __restrict__ W0,
           const float* __restrict__ W1,
           const float* __restrict__ P1, const float* __restrict__ P2,
           const float* __restrict__ P3, const float* __restrict__ P4,
           const float* __restrict__ P5, float* __restrict__ out)
{
    extern __shared__ char smc[];
    __half* sW0 = reinterpret_cast<__half*>(smc + O_W0);
    __half* sW1 = reinterpret_cast<__half*>(smc + O_W1);
    __half* sP  = reinterpret_cast<__half*>(smc + O_P);

    const int tid  = threadIdx.x;
    const int warp = tid >> 5;
    const int lane = tid & 31;

    // ---------------- stage all weights once (full block) ----------------
    for (int q = tid; q < 64 * 32; q += THREADS) {
        int k = q >> 5, c4 = (q & 31) * 4;
        st_h4(sW0 + k * LDW0 + c4, *(const float4*)(W0 + k * 128 + c4));
    }
    for (int q = tid; q < 128 * 32; q += THREADS) {
        int k = q >> 5, c4 = (q & 31) * 4;
        st_h4(sW1 + k * LDW1 + c4, *(const float4*)(W1 + k * 128 + c4));
    }
    {
        const float* Ps[5] = {P1, P2, P3, P4, P5};
        for (int q = tid; q < 128 * 80; q += THREADS) {
            int k  = q / 80;
            int j4 = (q % 80) * 4;
            int c  = j4 / 160, jj = j4 % 160;
            int p  = jj >> 5,  uu = jj & 31;
            st_h4(sP + k * LDP + j4,
                  *(const float4*)(Ps[p] + k * 64 + c * 32 + uu));
        }
    }
    __syncthreads();

    // ---------------- per-pipeline setup ----------------
    const int pid  = warp >> 2;            // 0..3
    const int wl   = warp & 3;             // warp within pipeline
    const int ltid = tid & 127;            // thread within pipeline
    const int bid  = pid + 1;              // named barrier id 1..4

    char* hB = smc + O_T + pid * HB;
    __half* sE  = reinterpret_cast<__half*>(hB + H_E);
    __half* sH1 = reinterpret_cast<__half*>(hB + H_H1);
    __half* sH2 = reinterpret_cast<__half*>(hB + H_H2);
    float*  sX  = reinterpret_cast<float*>(hB + H_X);
    float*  scr = sX + wl * (16 * LDS_SCR);

    // emb register double-buffer: 256 f4 per tile, thread covers ltid, ltid+128
    const int q0 = ltid, q1 = ltid + 128;
    const int er0 = q0 >> 4, ec0 = (q0 & 15) * 4;
    const int er1 = q1 >> 4, ec1 = (q1 & 15) * 4;
    float4 ea0, ea1;
    auto load_emb = [&](int t) {
        long g0 = (long)t * MT + er0;
        long g1 = (long)t * MT + er1;
        ea0 = *(const float4*)(emb + g0 * 64 + ec0);
        ea1 = *(const float4*)(emb + g1 * 64 + ec1);
    };

    const int w0 = blockIdx.x * NPIPE + pid;   // pipeline id 0..607
    if (w0 < TILES) load_emb(w0);

    const float s1  = 0.125f;
    const float s2  = 0.08838834764831845f;
    const float inv = 0.08838834764831845f;

    const float INV_SQRT2 = 0.7071067811865476f;
    const float INV_SQRT3 = 0.5773502691896258f;
    const float INV_SQRT6 = 0.4082482904638631f;

    const int cr = lane >> 1;
    const int cc = (lane & 1) * 16;

    for (int t = w0; t < TILES; t += NWORK) {
        // ---- STS emb tile; barrier also fences prior epilogue sX reads ----
        st_h4(sE + er0 * LDE + ec0, ea0);
        st_h4(sE + er1 * LDE + ec1, ea1);
        pbar(bid);
        if (t + NWORK < TILES) load_emb(t + NWORK);

        // ---- G1: emb @ W0 -> scratch -> silu -> sH1 ----
        {
            FragC acc[2];
            #pragma unroll
            for (int n = 0; n < 2; n++) wmma::fill_fragment(acc[n], 0.0f);
            #pragma unroll
            for (int k = 0; k < 64; k += 16) {
                FragA a;
                wmma::load_matrix_sync(a, sE + k, LDE);
                #pragma unroll
                for (int n = 0; n < 2; n++) {
                    FragB b;
                    wmma::load_matrix_sync(b, sW0 + k * LDW0 + wl * 32 + n * 16, LDW0);
                    wmma::mma_sync(acc[n], a, b, acc[n]);
                }
            }
            wmma::store_matrix_sync(scr,      acc[0], LDS_SCR, wmma::mem_row_major);
            wmma::store_matrix_sync(scr + 16, acc[1], LDS_SCR, wmma::mem_row_major);
            __syncwarp();
            const float* s = scr + cr * LDS_SCR + cc;
            __half* d = sH1 + cr * LDH + wl * 32 + cc;
            #pragma unroll
            for (int j = 0; j < 4; j++) {
                float4 v = *(const float4*)(s + j * 4);
                v.x = silu_f(v.x * s1); v.y = silu_f(v.y * s1);
                v.z = silu_f(v.z * s1); v.w = silu_f(v.w * s1);
                st_h4(d + j * 4, v);
            }
        }
        pbar(bid);

        // ---- G2: h1 @ W1 -> scratch -> silu*inv -> sH2 ----
        {
            FragC acc[2];
            #pragma unroll
            for (int n = 0; n < 2; n++) wmma::fill_fragment(acc[n], 0.0f);
            #pragma unroll
            for (int k = 0; k < 128; k += 16) {
                FragA a;
                wmma::load_matrix_sync(a, sH1 + k, LDH);
                #pragma unroll
                for (int n = 0; n < 2; n++) {
                    FragB b;
                    wmma::load_matrix_sync(b, sW1 + k * LDW1 + wl * 32 + n * 16, LDW1);
                    wmma::mma_sync(acc[n], a, b, acc[n]);
                }
            }
            wmma::store_matrix_sync(scr,      acc[0], LDS_SCR, wmma::mem_row_major);
            wmma::store_matrix_sync(scr + 16, acc[1], LDS_SCR, wmma::mem_row_major);
            __syncwarp();
            const float* s = scr + cr * LDS_SCR + cc;
            __half* d = sH2 + cr * LDH + wl * 32 + cc;
            #pragma unroll
            for (int j = 0; j < 4; j++) {
                float4 v = *(const float4*)(s + j * 4);
                v.x = silu_f(v.x * s2) * inv; v.y = silu_f(v.y * s2) * inv;
                v.z = silu_f(v.z * s2) * inv; v.w = silu_f(v.w * s2) * inv;
                st_h4(d + j * 4, v);
            }
        }
        pbar(bid);

        const long g0 = (long)t * MT;

        // ---- G3 + epilogue: 2 chunks of 160 cols (32 u each) ----
        #pragma unroll
        for (int c = 0; c < 2; c++) {
            // prefetch epilogue inputs (hide LDG under MMA)
            float x10v[4], av[12];
            float4 x2v[4];
            #pragma unroll
            for (int h = 0; h < 4; h++) {
                int idx = ltid + h * 128;         // 512 tasks: 16 rows x 32 u
                int r = idx >> 5, uu = idx & 31;
                int u = c * 32 + uu;
                long g = g0 + r;
                const float* x1r = x1 + g * 256;
                x10v[h]       = x1r[u];
                av[3 * h + 0] = x1r[64 + 3 * u + 0];
                av[3 * h + 1] = x1r[64 + 3 * u + 1];
                av[3 * h + 2] = x1r[64 + 3 * u + 2];
                x2v[h] = *(const float4*)(x2 + g * 4);
            }

            {   // w = h2 @ Pcat[c] : 10 n-tiles over 4 warps
                const int ncnt = (wl < 2) ? 3 : 2;
                FragC acc[3];
                for (int s = 0; s < ncnt; s++) wmma::fill_fragment(acc[s], 0.0f);
                #pragma unroll
                for (int k = 0; k < 128; k += 16) {
                    FragA a;
                    wmma::load_matrix_sync(a, sH2 + k, LDH);
                    for (int s = 0; s < ncnt; s++) {
                        int nt = wl + s * 4;
                        FragB b;
                        wmma::load_matrix_sync(b, sP + k * LDP + c * 160 + nt * 16, LDP);
                        wmma::mma_sync(acc[s], a, b, acc[s]);
                    }
                }
                for (int s = 0; s < ncnt; s++) {
                    int nt = wl + s * 4;
                    wmma::store_matrix_sync(sX + nt * 16, acc[s], LDX,
                                            wmma::mem_row_major);
                }
            }
            pbar(bid);

            // ---- epilogue ----
            #pragma unroll
            for (int h = 0; h < 4; h++) {
                int idx = ltid + h * 128;
                int r = idx >> 5, uu = idx & 31;
                int u = c * 32 + uu;
                long g = g0 + r;

                float b0 = x2v[h].x, c0v = x2v[h].y, c1v = x2v[h].z, c2v = x2v[h].w;
                float x10 = x10v[h];
                float a0 = av[3 * h + 0], a1 = av[3 * h + 1], a2 = av[3 * h + 2];

                const float* wr = sX + r * LDX;
                float w1 = wr[uu];
                float w2 = wr[32 + uu];
                float w3 = wr[64 + uu];
                float w4 = wr[96 + uu];
                float w5 = wr[128 + uu];

                float* o = out + g * 448;
                float dot = a0 * c0v + a1 * c1v + a2 * c2v;

                o[u] = INV_SQRT2 * (w1 * x10 * b0 + w4 * dot * INV_SQRT3);

                o[64 + 3 * u + 0] = INV_SQRT2 * (w2 * a0 * b0 + w3 * x10 * c0v);
                o[64 + 3 * u + 1] = INV_SQRT2 * (w2 * a1 * b0 + w3 * x10 * c1v);
                o[64 + 3 * u + 2] = INV_SQRT2 * (w2 * a2 * b0 + w3 * x10 * c2v);

                float r0 = a1 * c2v - a2 * c1v;
                float r1 = a2 * c0v - a0 * c2v;
                float r2 = a0 * c1v - a1 * c0v;
                o[256 + 3 * u + 0] = w5 * r0 * INV_SQRT6;
                o[256 + 3 * u + 1] = w5 * r1 * INV_SQRT6;
                o[256 + 3 * u + 2] = w5 * r2 * INV_SQRT6;
            }
            if (c == 0) pbar(bid);   // sX reused by chunk 1; loop-top barrier fences chunk-1 reads
        }
    }
}

extern "C" void kernel_launch(void* const* d_in, const int* in_sizes, int n_in,
                              void* d_out, int out_size) {
    (void)in_sizes; (void)n_in; (void)out_size;
    const float* emb = (const float*)d_in[0];
    const float* x1  = (const float*)d_in[1];
    const float* x2  = (const float*)d_in[2];
    const float* W0  = (const float*)d_in[3];
    const float* W1  = (const float*)d_in[4];
    const float* P1  = (const float*)d_in[5];
    const float* P2  = (const float*)d_in[6];
    const float* P3  = (const float*)d_in[7];
    const float* P4  = (const float*)d_in[8];
    const float* P5  = (const float*)d_in[9];
    float* out = (float*)d_out;

    cudaFuncSetAttribute(fused_fp16,
                         cudaFuncAttributeMaxDynamicSharedMemorySize, SMEM_BYTES);

    fused_fp16<<<NSM, THREADS, SMEM_BYTES>>>(emb, x1, x2, W0, W1,
                                             P1, P2, P3, P4, P5, out);
}

// round 13
// speedup vs baseline: 7.3602x; 1.0515x over previous
#include <cuda_runtime.h>
#include <cuda_fp16.h>
#include <mma.h>
#include <cstdint>

using namespace nvcuda;

namespace {
constexpr int E_TOT   = 100000;
constexpr int NSM     = 152;
constexpr int MT      = 16;                       // rows per pipeline tile
constexpr int TILES   = E_TOT / MT;               // 6250 exact
constexpr int NPIPE   = 4;
constexpr int NWORK   = NSM * NPIPE;              // 608 pipelines
constexpr int THREADS = 512;

// leading dims (elements)
constexpr int LDW0 = 136;   // halves
constexpr int LDW1 = 136;   // halves
constexpr int LDP  = 328;   // halves
constexpr int LDE  = 72;    // halves
constexpr int LDH  = 136;   // halves
constexpr int LDX  = 164;   // floats

// byte offsets
constexpr int O_W0 = 0;                           // 17408
constexpr int O_W1 = O_W0 + 64  * LDW0 * 2;       // 17408
constexpr int O_P  = O_W1 + 128 * LDW1 * 2;       // 52224
constexpr int O_T  = O_P  + 128 * LDP  * 2;       // 136192
// per-pipeline tile block
constexpr int H_E  = 0;                           // 16*72*2  = 2304
constexpr int H_H1 = H_E  + MT * LDE * 2;         // 2304
constexpr int H_H2 = H_H1 + MT * LDH * 2;         // 6656
constexpr int H_X  = H_H2 + MT * LDH * 2;         // 11008
constexpr int HB   = H_X  + MT * LDX * 4;         // 21504
constexpr int SMEM_BYTES = O_T + NPIPE * HB;      // 222208
}

__device__ __forceinline__ float silu_f(float x) {
    return __fdividef(x, 1.0f + __expf(-x));
}

using FragA  = wmma::fragment<wmma::matrix_a, 16, 16, 16, __half, wmma::row_major>;
using FragB  = wmma::fragment<wmma::matrix_b, 16, 16, 16, __half, wmma::row_major>;
using FragC  = wmma::fragment<wmma::accumulator, 16, 16, 16, float>;
using FragCH = wmma::fragment<wmma::accumulator, 16, 16, 16, __half>;

__device__ __forceinline__ void st_h4(__half* d, float4 v) {
    __half2 lo = __floats2half2_rn(v.x, v.y);
    __half2 hi = __floats2half2_rn(v.z, v.w);
    uint2 u;
    u.x = *reinterpret_cast<uint32_t*>(&lo);
    u.y = *reinterpret_cast<uint32_t*>(&hi);
    *reinterpret_cast<uint2*>(d) = u;
}
__device__ __forceinline__ void pbar(int id) {
    asm volatile("bar.sync %0, 128;" :: "r"(id) : "memory");
}

__global__ void __launch_bounds__(THREADS, 1)
fused_fp16(const float* __restrict__ emb, const float* __restrict__ x1,
           const float* __restrict__ x2, const float* __restrict__ W0,
           const float* __restrict__ W1,
           const float* __restrict__ P1, const float* __restrict__ P2,
           const float* __restrict__ P3, const float* __restrict__ P4,
           const float* __restrict__ P5, float* __restrict__ out)
{
    extern __shared__ char smc[];
    __half* sW0 = reinterpret_cast<__half*>(smc + O_W0);
    __half* sW1 = reinterpret_cast<__half*>(smc + O_W1);
    __half* sP  = reinterpret_cast<__half*>(smc + O_P);

    const int tid  = threadIdx.x;
    const int warp = tid >> 5;

    // ---------------- stage all weights once (full block) ----------------
    for (int q = tid; q < 64 * 32; q += THREADS) {
        int k = q >> 5, c4 = (q & 31) * 4;
        st_h4(sW0 + k * LDW0 + c4, *(const float4*)(W0 + k * 128 + c4));
    }
    for (int q = tid; q < 128 * 32; q += THREADS) {
        int k = q >> 5, c4 = (q & 31) * 4;
        st_h4(sW1 + k * LDW1 + c4, *(const float4*)(W1 + k * 128 + c4));
    }
    {
        const float* Ps[5] = {P1, P2, P3, P4, P5};
        for (int q = tid; q < 128 * 80; q += THREADS) {
            int k  = q / 80;
            int j4 = (q % 80) * 4;
            int c  = j4 / 160, jj = j4 % 160;
            int p  = jj >> 5,  uu = jj & 31;
            st_h4(sP + k * LDP + j4,
                  *(const float4*)(Ps[p] + k * 64 + c * 32 + uu));
        }
    }
    __syncthreads();

    // ---------------- per-pipeline setup ----------------
    const int pid  = warp >> 2;            // 0..3
    const int wl   = warp & 3;             // warp within pipeline
    const int ltid = tid & 127;            // thread within pipeline
    const int bid  = pid + 1;              // named barrier id 1..4

    char* hB = smc + O_T + pid * HB;
    __half* sE  = reinterpret_cast<__half*>(hB + H_E);
    __half* sH1 = reinterpret_cast<__half*>(hB + H_H1);
    __half* sH2 = reinterpret_cast<__half*>(hB + H_H2);
    float*  sX  = reinterpret_cast<float*>(hB + H_X);

    // emb register double-buffer: 256 f4 per tile, thread covers ltid, ltid+128
    const int q0 = ltid, q1 = ltid + 128;
    const int er0 = q0 >> 4, ec0 = (q0 & 15) * 4;
    const int er1 = q1 >> 4, ec1 = (q1 & 15) * 4;
    float4 ea0, ea1;
    auto load_emb = [&](int t) {
        long g0 = (long)t * MT + er0;
        long g1 = (long)t * MT + er1;
        ea0 = *(const float4*)(emb + g0 * 64 + ec0);
        ea1 = *(const float4*)(emb + g1 * 64 + ec1);
    };

    const int w0 = blockIdx.x * NPIPE + pid;   // pipeline id 0..607
    if (w0 < TILES) load_emb(w0);

    const float s1  = 0.125f;
    const float s2  = 0.08838834764831845f;
    const float inv = 0.08838834764831845f;

    const float INV_SQRT2 = 0.7071067811865476f;
    const float INV_SQRT3 = 0.5773502691896258f;
    const float INV_SQRT6 = 0.4082482904638631f;

    for (int t = w0; t < TILES; t += NWORK) {
        // ---- STS emb tile; barrier also fences prior epilogue sX reads ----
        st_h4(sE + er0 * LDE + ec0, ea0);
        st_h4(sE + er1 * LDE + ec1, ea1);
        pbar(bid);
        if (t + NWORK < TILES) load_emb(t + NWORK);

        // ---- G1: emb @ W0 -> silu in regs -> sH1 (fp16 direct) ----
        {
            FragC acc[2];
            #pragma unroll
            for (int n = 0; n < 2; n++) wmma::fill_fragment(acc[n], 0.0f);
            #pragma unroll
            for (int k = 0; k < 64; k += 16) {
                FragA a;
                wmma::load_matrix_sync(a, sE + k, LDE);
                #pragma unroll
                for (int n = 0; n < 2; n++) {
                    FragB b;
                    wmma::load_matrix_sync(b, sW0 + k * LDW0 + wl * 32 + n * 16, LDW0);
                    wmma::mma_sync(acc[n], a, b, acc[n]);
                }
            }
            #pragma unroll
            for (int n = 0; n < 2; n++) {
                FragCH ch;
                #pragma unroll
                for (int i = 0; i < acc[n].num_elements; i++)
                    ch.x[i] = __float2half(silu_f(acc[n].x[i] * s1));
                wmma::store_matrix_sync(sH1 + wl * 32 + n * 16, ch, LDH,
                                        wmma::mem_row_major);
            }
        }
        pbar(bid);

        // ---- G2: h1 @ W1 -> silu*inv in regs -> sH2 (fp16 direct) ----
        {
            FragC acc[2];
            #pragma unroll
            for (int n = 0; n < 2; n++) wmma::fill_fragment(acc[n], 0.0f);
            #pragma unroll
            for (int k = 0; k < 128; k += 16) {
                FragA a;
                wmma::load_matrix_sync(a, sH1 + k, LDH);
                #pragma unroll
                for (int n = 0; n < 2; n++) {
                    FragB b;
                    wmma::load_matrix_sync(b, sW1 + k * LDW1 + wl * 32 + n * 16, LDW1);
                    wmma::mma_sync(acc[n], a, b, acc[n]);
                }
            }
            #pragma unroll
            for (int n = 0; n < 2; n++) {
                FragCH ch;
                #pragma unroll
                for (int i = 0; i < acc[n].num_elements; i++)
                    ch.x[i] = __float2half(silu_f(acc[n].x[i] * s2) * inv);
                wmma::store_matrix_sync(sH2 + wl * 32 + n * 16, ch, LDH,
                                        wmma::mem_row_major);
            }
        }
        pbar(bid);

        const long g0 = (long)t * MT;

        // ---- G3 + epilogue: 2 chunks of 160 cols (32 u each) ----
        #pragma unroll
        for (int c = 0; c < 2; c++) {
            // prefetch epilogue inputs (hide LDG under MMA)
            float x10v[4], av[12];
            float4 x2v[4];
            #pragma unroll
            for (int h = 0; h < 4; h++) {
                int idx = ltid + h * 128;         // 512 tasks: 16 rows x 32 u
                int r = idx >> 5, uu = idx & 31;
                int u = c * 32 + uu;
                long g = g0 + r;
                const float* x1r = x1 + g * 256;
                x10v[h]       = x1r[u];
                av[3 * h + 0] = x1r[64 + 3 * u + 0];
                av[3 * h + 1] = x1r[64 + 3 * u + 1];
                av[3 * h + 2] = x1r[64 + 3 * u + 2];
                x2v[h] = *(const float4*)(x2 + g * 4);
            }

            {   // w = h2 @ Pcat[c] : 10 n-tiles over 4 warps
                const int ncnt = (wl < 2) ? 3 : 2;
                FragC acc[3];
                for (int s = 0; s < ncnt; s++) wmma::fill_fragment(acc[s], 0.0f);
                #pragma unroll
                for (int k = 0; k < 128; k += 16) {
                    FragA a;
                    wmma::load_matrix_sync(a, sH2 + k, LDH);
                    for (int s = 0; s < ncnt; s++) {
                        int nt = wl + s * 4;
                        FragB b;
                        wmma::load_matrix_sync(b, sP + k * LDP + c * 160 + nt * 16, LDP);
                        wmma::mma_sync(acc[s], a, b, acc[s]);
                    }
                }
                for (int s = 0; s < ncnt; s++) {
                    int nt = wl + s * 4;
                    wmma::store_matrix_sync(sX + nt * 16, acc[s], LDX,
                                            wmma::mem_row_major);
                }
            }
            pbar(bid);

            // ---- epilogue ----
            #pragma unroll
            for (int h = 0; h < 4; h++) {
                int idx = ltid + h * 128;
                int r = idx >> 5, uu = idx & 31;
                int u = c * 32 + uu;
                long g = g0 + r;

                float b0 = x2v[h].x, c0v = x2v[h].y, c1v = x2v[h].z, c2v = x2v[h].w;
                float x10 = x10v[h];
                float a0 = av[3 * h + 0], a1 = av[3 * h + 1], a2 = av[3 * h + 2];

                const float* wr = sX + r * LDX;
                float w1 = wr[uu];
                float w2 = wr[32 + uu];
                float w3 = wr[64 + uu];
                float w4 = wr[96 + uu];
                float w5 = wr[128 + uu];

                float* o = out + g * 448;
                float dot = a0 * c0v + a1 * c1v + a2 * c2v;

                o[u] = INV_SQRT2 * (w1 * x10 * b0 + w4 * dot * INV_SQRT3);

                o[64 + 3 * u + 0] = INV_SQRT2 * (w2 * a0 * b0 + w3 * x10 * c0v);
                o[64 + 3 * u + 1] = INV_SQRT2 * (w2 * a1 * b0 + w3 * x10 * c1v);
                o[64 + 3 * u + 2] = INV_SQRT2 * (w2 * a2 * b0 + w3 * x10 * c2v);

                float r0 = a1 * c2v - a2 * c1v;
                float r1 = a2 * c0v - a0 * c2v;
                float r2 = a0 * c1v - a1 * c0v;
                o[256 + 3 * u + 0] = w5 * r0 * INV_SQRT6;
                o[256 + 3 * u + 1] = w5 * r1 * INV_SQRT6;
                o[256 + 3 * u + 2] = w5 * r2 * INV_SQRT6;
            }
            if (c == 0) pbar(bid);   // sX reused by chunk 1; loop-top barrier fences chunk-1 reads
        }
    }
}

extern "C" void kernel_launch(void* const* d_in, const int* in_sizes, int n_in,
                              void* d_out, int out_size) {
    (void)in_sizes; (void)n_in; (void)out_size;
    const float* emb = (const float*)d_in[0];
    const float* x1  = (const float*)d_in[1];
    const float* x2  = (const float*)d_in[2];
    const float* W0  = (const float*)d_in[3];
    const float* W1  = (const float*)d_in[4];
    const float* P1  = (const float*)d_in[5];
    const float* P2  = (const float*)d_in[6];
    const float* P3  = (const float*)d_in[7];
    const float* P4  = (const float*)d_in[8];
    const float* P5  = (const float*)d_in[9];
    float* out = (float*)d_out;

    cudaFuncSetAttribute(fused_fp16,
                         cudaFuncAttributeMaxDynamicSharedMemorySize, SMEM_BYTES);

    fused_fp16<<<NSM, THREADS, SMEM_BYTES>>>(emb, x1, x2, W0, W1,
                                             P1, P2, P3, P4, P5, out);
}